// round 16
// baseline (speedup 1.0000x reference)
#include <cuda_runtime.h>

// Scratch (device globals — no allocation allowed).
// g_F: pooled means, TRANSPOSED layout [bs][3][512] (bs 0..63 x, 64..127 y).
// g_Z: VN-MLP activated output, TRANSPOSED layout [bs][3][512].
static __device__ float g_F[128 * 3 * 512];
static __device__ float g_Z[128 * 3 * 512];

// ---------------------------------------------------------------------------
// Kernel 1 (fused): mean over point dim for ALL 8 tensors in one launch.
// One warp per row; n=64 rows pack 2 per warp. Shuffle-only reduce, __ldcs.
// Writes g_F transposed. (~6.7 TB/s — at the practical streaming ceiling.)
// ---------------------------------------------------------------------------
struct MeanArgs {
    const float* src[8];
    int   n4[8];
    float inv_n[8];
    int   chan[8];
    int   chan_off[8];
    int   bs_off[8];
    int   warp_base[9];
};

__global__ void __launch_bounds__(256) mean_fused_kernel(MeanArgs A) {
    int w = blockIdx.x * 8 + (threadIdx.x >> 5);
    int lane = threadIdx.x & 31;
    if (w >= A.warp_base[8]) return;

    int t = 0;
#pragma unroll
    for (int i = 1; i < 8; ++i) t += (w >= A.warp_base[i]) ? 1 : 0;
    int lw = w - A.warp_base[t];
    int n4 = A.n4[t];
    const float4* p = reinterpret_cast<const float4*>(A.src[t]);

    int row;
    float s = 0.f;
    bool writer;

    if (n4 >= 32) {
        row = lw;
        const float4* q = p + (long long)row * n4;
#pragma unroll 8
        for (int i = lane; i < n4; i += 32) {
            float4 v = __ldcs(q + i);
            s += (v.x + v.y) + (v.z + v.w);
        }
#pragma unroll
        for (int off = 16; off > 0; off >>= 1)
            s += __shfl_xor_sync(0xffffffffu, s, off);
        writer = (lane == 0);
    } else {
        row = lw * 2 + (lane >> 4);
        int sl = lane & 15;
        float4 v = __ldcs(p + (long long)row * 16 + sl);
        s = (v.x + v.y) + (v.z + v.w);
#pragma unroll
        for (int off = 8; off > 0; off >>= 1)
            s += __shfl_xor_sync(0xffffffffu, s, off);
        writer = (sl == 0);
    }

    if (writer) {
        int chan = A.chan[t];
        int d = row % 3;
        int c = (row / 3) % chan;
        int b = row / (3 * chan);
        g_F[((A.bs_off[t] + b) * 3 + d) * 512 + (A.chan_off[t] + c)] = s * A.inv_n[t];
    }
}

// ---------------------------------------------------------------------------
// Kernel 2: VN-MLP, packed f32x2 FMAs — HIGH-OCCUPANCY version.
// Warp = 1 output (acc 12 regs, W cache 32 regs) -> body fits 85 regs ->
// __launch_bounds__(256,3): 3 blocks/SM, 24 warps/SM (was 16).
// Grid (64 o-tiles of 8, 16 bs-tiles of 8) = 1024 blocks, 48KB static smem.
// Butterfly: 6 values padded to 8 -> 9 SHFLs reduce-scatter; lane L holds
// value bits L[4:2]; 6 broadcast-gathers; lane 0 epilogue.
// ---------------------------------------------------------------------------
union F4U { float4 f4; unsigned long long u[2]; float f[4]; };

__device__ __forceinline__ void ffma2(unsigned long long& d,
                                      unsigned long long a, unsigned long long b) {
    asm("fma.rn.f32x2 %0, %1, %2, %0;" : "+l"(d) : "l"(a), "l"(b));
}

__global__ void __launch_bounds__(256, 3) vnmlp_kernel(const float* __restrict__ W,
                                                       const float* __restrict__ Wd) {
    __shared__ float Fs[8 * 1536];   // [bs][dim][512] = 48KB
    int bs0 = blockIdx.y * 8;
    const float4* src4 = reinterpret_cast<const float4*>(g_F + bs0 * 1536);
    float4* Fs4 = reinterpret_cast<float4*>(Fs);
#pragma unroll
    for (int i = 0; i < 12; ++i)
        Fs4[threadIdx.x + i * 256] = src4[threadIdx.x + i * 256];

    int warp = threadIdx.x >> 5, lane = threadIdx.x & 31;
    int o = blockIdx.x * 8 + warp;      // this warp's single output row

    // Register-cache W / W_dir for this warp's output (overlaps smem fill).
    F4U wr[4], wdr[4];
#pragma unroll
    for (int st = 0; st < 4; ++st) {
        int idx = st * 32 + lane;
        wr[st].f4  = __ldg(reinterpret_cast<const float4*>(W  + o * 512) + idx);
        wdr[st].f4 = __ldg(reinterpret_cast<const float4*>(Wd + o * 512) + idx);
    }
    __syncthreads();

#pragma unroll 2
    for (int bs = 0; bs < 8; ++bs) {
        unsigned long long acc[6];
#pragma unroll
        for (int v = 0; v < 6; ++v) acc[v] = 0ull;

        const float* Fb = Fs + bs * 1536;
#pragma unroll
        for (int st = 0; st < 4; ++st) {
            int idx = st * 32 + lane;
            F4U f0, f1, f2;
            f0.f4 = reinterpret_cast<const float4*>(Fb)[idx];
            f1.f4 = reinterpret_cast<const float4*>(Fb + 512)[idx];
            f2.f4 = reinterpret_cast<const float4*>(Fb + 1024)[idx];
#pragma unroll
            for (int h = 0; h < 2; ++h) {
                ffma2(acc[0], wr[st].u[h],  f0.u[h]);
                ffma2(acc[1], wr[st].u[h],  f1.u[h]);
                ffma2(acc[2], wr[st].u[h],  f2.u[h]);
                ffma2(acc[3], wdr[st].u[h], f0.u[h]);
                ffma2(acc[4], wdr[st].u[h], f1.u[h]);
                ffma2(acc[5], wdr[st].u[h], f2.u[h]);
            }
        }

        // Fold f32x2 halves -> 6 scalars, pad to 8.
        float v[8];
#pragma unroll
        for (int c = 0; c < 6; ++c) {
            unsigned int lo = (unsigned int)(acc[c] & 0xffffffffull);
            unsigned int hi = (unsigned int)(acc[c] >> 32);
            v[c] = __uint_as_float(lo) + __uint_as_float(hi);
        }
        v[6] = 0.f; v[7] = 0.f;

        // Reduce-scatter over 8 values: lane L ends holding value bits L[4:2].
#pragma unroll
        for (int i = 0; i < 4; ++i) {
            float send = (lane & 16) ? v[i] : v[i + 4];
            float recv = __shfl_xor_sync(0xffffffffu, send, 16);
            v[i] = ((lane & 16) ? v[i + 4] : v[i]) + recv;
        }
#pragma unroll
        for (int i = 0; i < 2; ++i) {
            float send = (lane & 8) ? v[i] : v[i + 2];
            float recv = __shfl_xor_sync(0xffffffffu, send, 8);
            v[i] = ((lane & 8) ? v[i + 2] : v[i]) + recv;
        }
        {
            float send = (lane & 4) ? v[0] : v[1];
            float recv = __shfl_xor_sync(0xffffffffu, send, 4);
            v[0] = ((lane & 4) ? v[1] : v[0]) + recv;
        }
        v[0] += __shfl_xor_sync(0xffffffffu, v[0], 2);
        v[0] += __shfl_xor_sync(0xffffffffu, v[0], 1);

        // Broadcast-gather value i from lane i*4 (bits [4:2] = i).
        float r[6];
#pragma unroll
        for (int i = 0; i < 6; ++i)
            r[i] = __shfl_sync(0xffffffffu, v[0], i << 2);

        if (lane == 0) {
            float px = r[0], py = r[1], pz = r[2];
            float dx = r[3], dy = r[4], dz = r[5];
            float dot = px * dx + py * dy + pz * dz;
            float d2  = dx * dx + dy * dy + dz * dz;
            float coef = (dot >= 0.f) ? 0.f : 0.8f * dot / (d2 + 1e-6f);
            float* out = g_Z + (bs0 + bs) * 1536 + o;
            out[0]    = px - coef * dx;
            out[512]  = py - coef * dy;
            out[1024] = pz - coef * dz;
        }
    }
}

// ---------------------------------------------------------------------------
// Kernel 3: per-batch Kabsch (64 parallel blocks, 128 threads).
// Each thread owns exactly 4 channels: 6 coalesced LDG.128 total.
// fp64 moments; polar factor via Newton (4 scaled + 2 plain fp32, 2 fp64).
// ---------------------------------------------------------------------------
__global__ void kabsch_kernel(const float* __restrict__ mu_x,
                              const float* __restrict__ mu_y,
                              float* __restrict__ out) {
    __shared__ double smr[4][11];
    int b = blockIdx.x;
    int tid = threadIdx.x;
    float mx[3], my[3];
#pragma unroll
    for (int d = 0; d < 3; ++d) { mx[d] = mu_x[b * 3 + d]; my[d] = mu_y[b * 3 + d]; }
    const float* zx = g_Z + b * 1536;
    const float* zy = g_Z + (64 + b) * 1536;

    F4U xv[3], yv[3];
#pragma unroll
    for (int d = 0; d < 3; ++d) {
        xv[d].f4 = *reinterpret_cast<const float4*>(zx + d * 512 + tid * 4);
        yv[d].f4 = *reinterpret_cast<const float4*>(zy + d * 512 + tid * 4);
    }

    double a[11];
#pragma unroll
    for (int i = 0; i < 11; ++i) a[i] = 0.0;

#pragma unroll
    for (int j = 0; j < 4; ++j) {
        double xc[3], yc[3];
#pragma unroll
        for (int d = 0; d < 3; ++d) {
            xc[d] = (double)(xv[d].f[j] - mx[d]);
            yc[d] = (double)(yv[d].f[j] - my[d]);
        }
#pragma unroll
        for (int d = 0; d < 3; ++d)
#pragma unroll
            for (int e = 0; e < 3; ++e)
                a[d * 3 + e] += xc[d] * yc[e];
        a[9]  += xc[0] * xc[0] + xc[1] * xc[1] + xc[2] * xc[2];
        a[10] += yc[0] * yc[0] + yc[1] * yc[1] + yc[2] * yc[2];
    }

#pragma unroll
    for (int i = 0; i < 11; ++i)
        for (int off = 16; off > 0; off >>= 1)
            a[i] += __shfl_xor_sync(0xffffffffu, a[i], off);
    int warp = tid >> 5, lane = tid & 31;
    if (lane == 0)
        for (int i = 0; i < 11; ++i) smr[warp][i] = a[i];
    __syncthreads();

    if (tid == 0) {
        for (int i = 0; i < 11; ++i)
            a[i] = (smr[0][i] + smr[1][i]) + (smr[2][i] + smr[3][i]);

        float X[9];
        for (int i = 0; i < 9; ++i) X[i] = (float)a[i];
        for (int it = 0; it < 6; ++it) {
            float C[9];
            C[0] = X[4] * X[8] - X[5] * X[7];
            C[1] = X[5] * X[6] - X[3] * X[8];
            C[2] = X[3] * X[7] - X[4] * X[6];
            C[3] = X[2] * X[7] - X[1] * X[8];
            C[4] = X[0] * X[8] - X[2] * X[6];
            C[5] = X[1] * X[6] - X[0] * X[7];
            C[6] = X[1] * X[5] - X[2] * X[4];
            C[7] = X[2] * X[3] - X[0] * X[5];
            C[8] = X[0] * X[4] - X[1] * X[3];
            float det = X[0] * C[0] + X[1] * C[1] + X[2] * C[2];
            float invdet = 1.0f / det;
            float mu = 1.0f, inv_mu = 1.0f;
            if (it < 4) {
                float fx2 = (((X[0]*X[0] + X[1]*X[1]) + (X[2]*X[2] + X[3]*X[3]))
                          +  ((X[4]*X[4] + X[5]*X[5]) + (X[6]*X[6] + X[7]*X[7]))) + X[8]*X[8];
                float fc2 = (((C[0]*C[0] + C[1]*C[1]) + (C[2]*C[2] + C[3]*C[3]))
                          +  ((C[4]*C[4] + C[5]*C[5]) + (C[6]*C[6] + C[7]*C[7]))) + C[8]*C[8];
                float fy2 = fc2 * invdet * invdet;
                mu = sqrtf(sqrtf(fy2 / fx2));
                inv_mu = 1.0f / mu;
            }
#pragma unroll
            for (int i = 0; i < 9; ++i)
                X[i] = 0.5f * (mu * X[i] + inv_mu * C[i] * invdet);
        }

        double Y[9];
        for (int i = 0; i < 9; ++i) Y[i] = (double)X[i];
        for (int it = 0; it < 2; ++it) {
            double C[9];
            C[0] = Y[4] * Y[8] - Y[5] * Y[7];
            C[1] = Y[5] * Y[6] - Y[3] * Y[8];
            C[2] = Y[3] * Y[7] - Y[4] * Y[6];
            C[3] = Y[2] * Y[7] - Y[1] * Y[8];
            C[4] = Y[0] * Y[8] - Y[2] * Y[6];
            C[5] = Y[1] * Y[6] - Y[0] * Y[7];
            C[6] = Y[1] * Y[5] - Y[2] * Y[4];
            C[7] = Y[2] * Y[3] - Y[0] * Y[5];
            C[8] = Y[0] * Y[4] - Y[1] * Y[3];
            double det = Y[0] * C[0] + Y[1] * C[1] + Y[2] * C[2];
            double invdet = 1.0 / det;
#pragma unroll
            for (int i = 0; i < 9; ++i)
                Y[i] = 0.5 * (Y[i] + C[i] * invdet);
        }

        for (int i = 0; i < 9; ++i) out[b * 9 + i] = (float)Y[i];
        double t0 = (double)my[0] - (Y[0] * mx[0] + Y[1] * mx[1] + Y[2] * mx[2]);
        double t1 = (double)my[1] - (Y[3] * mx[0] + Y[4] * mx[1] + Y[5] * mx[2]);
        double t2 = (double)my[2] - (Y[6] * mx[0] + Y[7] * mx[1] + Y[8] * mx[2]);
        out[576 + b * 3 + 0] = (float)t0;
        out[576 + b * 3 + 1] = (float)t1;
        out[576 + b * 3 + 2] = (float)t2;
        double xn = sqrt(a[9]), yn = sqrt(a[10]);
        out[768 + b] = (float)(yn / (xn + 1e-6));
    }
}

// ---------------------------------------------------------------------------
extern "C" void kernel_launch(void* const* d_in, const int* in_sizes, int n_in,
                              void* d_out, int out_size) {
    int xi[4], yi[4];
    if (in_sizes[0] == in_sizes[1]) {
        for (int i = 0; i < 4; ++i) { xi[i] = 2 * i; yi[i] = 2 * i + 1; }
    } else {
        for (int i = 0; i < 4; ++i) { xi[i] = i; yi[i] = 4 + i; }
    }
    const float* mu_x = (const float*)d_in[8];
    const float* mu_y = (const float*)d_in[9];
    const float* W    = (const float*)d_in[10];
    const float* Wd   = (const float*)d_in[11];

    static const int chans[4] = {64, 128, 128, 192};
    static const int npts[4]  = {4096, 1024, 256, 64};
    static const int choff[4] = {0, 64, 192, 320};

    MeanArgs A;
    int wb = 0;
    for (int i = 0; i < 4; ++i) {
        for (int side = 0; side < 2; ++side) {
            int t = i * 2 + side;
            A.src[t]      = (const float*)d_in[side == 0 ? xi[i] : yi[i]];
            A.n4[t]       = npts[i] >> 2;
            A.inv_n[t]    = 1.0f / (float)npts[i];
            A.chan[t]     = chans[i];
            A.chan_off[t] = choff[i];
            A.bs_off[t]   = side == 0 ? 0 : 64;
            A.warp_base[t] = wb;
            int rows = 64 * chans[i] * 3;
            wb += (npts[i] == 64) ? rows / 2 : rows;
        }
    }
    A.warp_base[8] = wb;

    mean_fused_kernel<<<(wb + 7) / 8, 256>>>(A);
    vnmlp_kernel<<<dim3(64, 16), 256>>>(W, Wd);
    kabsch_kernel<<<64, 128>>>(mu_x, mu_y, (float*)d_out);
}

// round 17
// speedup vs baseline: 1.0360x; 1.0360x over previous
#include <cuda_runtime.h>

// Scratch (device globals — no allocation allowed).
// g_F: pooled means, TRANSPOSED layout [bs][3][512] (bs 0..63 x, 64..127 y).
// g_Z: VN-MLP activated output, TRANSPOSED layout [bs][3][512].
static __device__ float g_F[128 * 3 * 512];
static __device__ float g_Z[128 * 3 * 512];

// ---------------------------------------------------------------------------
// Kernel 1 (fused): mean over point dim for ALL 8 tensors in one launch.
// One warp per row; n=64 rows pack 2 per warp. Shuffle-only reduce, __ldcs.
// Writes g_F transposed. (~6.7 TB/s — at the practical streaming ceiling.)
// ---------------------------------------------------------------------------
struct MeanArgs {
    const float* src[8];
    int   n4[8];
    float inv_n[8];
    int   chan[8];
    int   chan_off[8];
    int   bs_off[8];
    int   warp_base[9];
};

__global__ void __launch_bounds__(256) mean_fused_kernel(MeanArgs A) {
    int w = blockIdx.x * 8 + (threadIdx.x >> 5);
    int lane = threadIdx.x & 31;
    if (w >= A.warp_base[8]) return;

    int t = 0;
#pragma unroll
    for (int i = 1; i < 8; ++i) t += (w >= A.warp_base[i]) ? 1 : 0;
    int lw = w - A.warp_base[t];
    int n4 = A.n4[t];
    const float4* p = reinterpret_cast<const float4*>(A.src[t]);

    int row;
    float s = 0.f;
    bool writer;

    if (n4 >= 32) {
        row = lw;
        const float4* q = p + (long long)row * n4;
#pragma unroll 8
        for (int i = lane; i < n4; i += 32) {
            float4 v = __ldcs(q + i);
            s += (v.x + v.y) + (v.z + v.w);
        }
#pragma unroll
        for (int off = 16; off > 0; off >>= 1)
            s += __shfl_xor_sync(0xffffffffu, s, off);
        writer = (lane == 0);
    } else {
        row = lw * 2 + (lane >> 4);
        int sl = lane & 15;
        float4 v = __ldcs(p + (long long)row * 16 + sl);
        s = (v.x + v.y) + (v.z + v.w);
#pragma unroll
        for (int off = 8; off > 0; off >>= 1)
            s += __shfl_xor_sync(0xffffffffu, s, off);
        writer = (sl == 0);
    }

    if (writer) {
        int chan = A.chan[t];
        int d = row % 3;
        int c = (row / 3) % chan;
        int b = row / (3 * chan);
        g_F[((A.bs_off[t] + b) * 3 + d) * 512 + (A.chan_off[t] + c)] = s * A.inv_n[t];
    }
}

// ---------------------------------------------------------------------------
// Kernel 2: VN-MLP, packed f32x2 FMAs. (R12 body + paired-pass butterfly.)
// Grid (32 o-tiles of 16, 16 bs-tiles of 8), 256 threads, min 2 blocks/SM.
// Warp = 2 outputs; W/W_dir register-cached; conflict-free float4 smem fill.
// bs-passes processed in PAIRS: one 24-value (pad 32) reduce-scatter
// butterfly (31 SHFLs) + 6 gather SHFLs serves both passes; epilogue on
// 4 lanes (lane = pass*2 + output). Halves serial chains per warp.
// ---------------------------------------------------------------------------
union F4U { float4 f4; unsigned long long u[2]; float f[4]; };

__device__ __forceinline__ void ffma2(unsigned long long& d,
                                      unsigned long long a, unsigned long long b) {
    asm("fma.rn.f32x2 %0, %1, %2, %0;" : "+l"(d) : "l"(a), "l"(b));
}

__global__ void __launch_bounds__(256, 2) vnmlp_kernel(const float* __restrict__ W,
                                                       const float* __restrict__ Wd) {
    __shared__ float Fs[8 * 1536];   // [bs][dim][512] = 48KB
    int bs0 = blockIdx.y * 8;
    const float4* src4 = reinterpret_cast<const float4*>(g_F + bs0 * 1536);
    float4* Fs4 = reinterpret_cast<float4*>(Fs);
#pragma unroll
    for (int i = 0; i < 12; ++i)
        Fs4[threadIdx.x + i * 256] = src4[threadIdx.x + i * 256];

    int warp = threadIdx.x >> 5, lane = threadIdx.x & 31;
    int o0 = blockIdx.x * 16 + warp * 2;

    // Register-cache W / W_dir for this warp's 2 outputs (overlaps smem fill).
    F4U wr[2][4], wdr[2][4];
#pragma unroll
    for (int j = 0; j < 2; ++j)
#pragma unroll
        for (int st = 0; st < 4; ++st) {
            int idx = st * 32 + lane;
            wr[j][st].f4  = __ldg(reinterpret_cast<const float4*>(W  + (o0 + j) * 512) + idx);
            wdr[j][st].f4 = __ldg(reinterpret_cast<const float4*>(Wd + (o0 + j) * 512) + idx);
        }
    __syncthreads();

    for (int bsp = 0; bsp < 4; ++bsp) {
        float vv[32];

        // Accumulate the two passes of this pair; fold each into vv[p*12 ..].
#pragma unroll
        for (int p = 0; p < 2; ++p) {
            int bs = bsp * 2 + p;
            unsigned long long acc[2][6];
#pragma unroll
            for (int j = 0; j < 2; ++j)
#pragma unroll
                for (int v = 0; v < 6; ++v) acc[j][v] = 0ull;

            const float* Fb = Fs + bs * 1536;
#pragma unroll
            for (int st = 0; st < 4; ++st) {
                int idx = st * 32 + lane;
                F4U f0, f1, f2;
                f0.f4 = reinterpret_cast<const float4*>(Fb)[idx];
                f1.f4 = reinterpret_cast<const float4*>(Fb + 512)[idx];
                f2.f4 = reinterpret_cast<const float4*>(Fb + 1024)[idx];
#pragma unroll
                for (int j = 0; j < 2; ++j)
#pragma unroll
                    for (int h = 0; h < 2; ++h) {
                        ffma2(acc[j][0], wr[j][st].u[h],  f0.u[h]);
                        ffma2(acc[j][1], wr[j][st].u[h],  f1.u[h]);
                        ffma2(acc[j][2], wr[j][st].u[h],  f2.u[h]);
                        ffma2(acc[j][3], wdr[j][st].u[h], f0.u[h]);
                        ffma2(acc[j][4], wdr[j][st].u[h], f1.u[h]);
                        ffma2(acc[j][5], wdr[j][st].u[h], f2.u[h]);
                    }
            }
#pragma unroll
            for (int j = 0; j < 2; ++j)
#pragma unroll
                for (int c = 0; c < 6; ++c) {
                    unsigned int lo = (unsigned int)(acc[j][c] & 0xffffffffull);
                    unsigned int hi = (unsigned int)(acc[j][c] >> 32);
                    vv[p * 12 + j * 6 + c] = __uint_as_float(lo) + __uint_as_float(hi);
                }
        }
#pragma unroll
        for (int i = 24; i < 32; ++i) vv[i] = 0.f;

        // Combined reduce-scatter over 32 slots: lane L ends holding value L.
#pragma unroll
        for (int i = 0; i < 16; ++i) {
            float send = (lane & 16) ? vv[i] : vv[i + 16];
            float recv = __shfl_xor_sync(0xffffffffu, send, 16);
            vv[i] = ((lane & 16) ? vv[i + 16] : vv[i]) + recv;
        }
#pragma unroll
        for (int i = 0; i < 8; ++i) {
            float send = (lane & 8) ? vv[i] : vv[i + 8];
            float recv = __shfl_xor_sync(0xffffffffu, send, 8);
            vv[i] = ((lane & 8) ? vv[i + 8] : vv[i]) + recv;
        }
#pragma unroll
        for (int i = 0; i < 4; ++i) {
            float send = (lane & 4) ? vv[i] : vv[i + 4];
            float recv = __shfl_xor_sync(0xffffffffu, send, 4);
            vv[i] = ((lane & 4) ? vv[i + 4] : vv[i]) + recv;
        }
#pragma unroll
        for (int i = 0; i < 2; ++i) {
            float send = (lane & 2) ? vv[i] : vv[i + 2];
            float recv = __shfl_xor_sync(0xffffffffu, send, 2);
            vv[i] = ((lane & 2) ? vv[i + 2] : vv[i]) + recv;
        }
        {
            float send = (lane & 1) ? vv[0] : vv[1];
            float recv = __shfl_xor_sync(0xffffffffu, send, 1);
            vv[0] = ((lane & 1) ? vv[1] : vv[0]) + recv;
        }

        // Gather: lane l<4 -> (pass p = l>>1, output j = l&1); value idx lives
        // on lane idx itself.
        float r[6];
#pragma unroll
        for (int i = 0; i < 6; ++i) {
            int src = ((lane >> 1) * 12 + (lane & 1) * 6 + i) & 31;
            r[i] = __shfl_sync(0xffffffffu, vv[0], src);
        }

        if (lane < 4) {
            float px = r[0], py = r[1], pz = r[2];
            float dx = r[3], dy = r[4], dz = r[5];
            float dot = px * dx + py * dy + pz * dz;
            float d2  = dx * dx + dy * dy + dz * dz;
            float coef = (dot >= 0.f) ? 0.f : 0.8f * dot / (d2 + 1e-6f);
            int bs = bsp * 2 + (lane >> 1);
            float* o = g_Z + (bs0 + bs) * 1536 + (o0 + (lane & 1));
            o[0]    = px - coef * dx;
            o[512]  = py - coef * dy;
            o[1024] = pz - coef * dz;
        }
    }
}

// ---------------------------------------------------------------------------
// Kernel 3: per-batch Kabsch (64 parallel blocks, 128 threads).
// Each thread owns exactly 4 channels: 6 coalesced LDG.128 total.
// fp64 moments; polar factor via Newton (4 scaled + 2 plain fp32, 2 fp64).
// ---------------------------------------------------------------------------
__global__ void kabsch_kernel(const float* __restrict__ mu_x,
                              const float* __restrict__ mu_y,
                              float* __restrict__ out) {
    __shared__ double smr[4][11];
    int b = blockIdx.x;
    int tid = threadIdx.x;
    float mx[3], my[3];
#pragma unroll
    for (int d = 0; d < 3; ++d) { mx[d] = mu_x[b * 3 + d]; my[d] = mu_y[b * 3 + d]; }
    const float* zx = g_Z + b * 1536;
    const float* zy = g_Z + (64 + b) * 1536;

    F4U xv[3], yv[3];
#pragma unroll
    for (int d = 0; d < 3; ++d) {
        xv[d].f4 = *reinterpret_cast<const float4*>(zx + d * 512 + tid * 4);
        yv[d].f4 = *reinterpret_cast<const float4*>(zy + d * 512 + tid * 4);
    }

    double a[11];
#pragma unroll
    for (int i = 0; i < 11; ++i) a[i] = 0.0;

#pragma unroll
    for (int j = 0; j < 4; ++j) {
        double xc[3], yc[3];
#pragma unroll
        for (int d = 0; d < 3; ++d) {
            xc[d] = (double)(xv[d].f[j] - mx[d]);
            yc[d] = (double)(yv[d].f[j] - my[d]);
        }
#pragma unroll
        for (int d = 0; d < 3; ++d)
#pragma unroll
            for (int e = 0; e < 3; ++e)
                a[d * 3 + e] += xc[d] * yc[e];
        a[9]  += xc[0] * xc[0] + xc[1] * xc[1] + xc[2] * xc[2];
        a[10] += yc[0] * yc[0] + yc[1] * yc[1] + yc[2] * yc[2];
    }

#pragma unroll
    for (int i = 0; i < 11; ++i)
        for (int off = 16; off > 0; off >>= 1)
            a[i] += __shfl_xor_sync(0xffffffffu, a[i], off);
    int warp = tid >> 5, lane = tid & 31;
    if (lane == 0)
        for (int i = 0; i < 11; ++i) smr[warp][i] = a[i];
    __syncthreads();

    if (tid == 0) {
        for (int i = 0; i < 11; ++i)
            a[i] = (smr[0][i] + smr[1][i]) + (smr[2][i] + smr[3][i]);

        float X[9];
        for (int i = 0; i < 9; ++i) X[i] = (float)a[i];
        for (int it = 0; it < 6; ++it) {
            float C[9];
            C[0] = X[4] * X[8] - X[5] * X[7];
            C[1] = X[5] * X[6] - X[3] * X[8];
            C[2] = X[3] * X[7] - X[4] * X[6];
            C[3] = X[2] * X[7] - X[1] * X[8];
            C[4] = X[0] * X[8] - X[2] * X[6];
            C[5] = X[1] * X[6] - X[0] * X[7];
            C[6] = X[1] * X[5] - X[2] * X[4];
            C[7] = X[2] * X[3] - X[0] * X[5];
            C[8] = X[0] * X[4] - X[1] * X[3];
            float det = X[0] * C[0] + X[1] * C[1] + X[2] * C[2];
            float invdet = 1.0f / det;
            float mu = 1.0f, inv_mu = 1.0f;
            if (it < 4) {
                float fx2 = (((X[0]*X[0] + X[1]*X[1]) + (X[2]*X[2] + X[3]*X[3]))
                          +  ((X[4]*X[4] + X[5]*X[5]) + (X[6]*X[6] + X[7]*X[7]))) + X[8]*X[8];
                float fc2 = (((C[0]*C[0] + C[1]*C[1]) + (C[2]*C[2] + C[3]*C[3]))
                          +  ((C[4]*C[4] + C[5]*C[5]) + (C[6]*C[6] + C[7]*C[7]))) + C[8]*C[8];
                float fy2 = fc2 * invdet * invdet;
                mu = sqrtf(sqrtf(fy2 / fx2));
                inv_mu = 1.0f / mu;
            }
#pragma unroll
            for (int i = 0; i < 9; ++i)
                X[i] = 0.5f * (mu * X[i] + inv_mu * C[i] * invdet);
        }

        double Y[9];
        for (int i = 0; i < 9; ++i) Y[i] = (double)X[i];
        for (int it = 0; it < 2; ++it) {
            double C[9];
            C[0] = Y[4] * Y[8] - Y[5] * Y[7];
            C[1] = Y[5] * Y[6] - Y[3] * Y[8];
            C[2] = Y[3] * Y[7] - Y[4] * Y[6];
            C[3] = Y[2] * Y[7] - Y[1] * Y[8];
            C[4] = Y[0] * Y[8] - Y[2] * Y[6];
            C[5] = Y[1] * Y[6] - Y[0] * Y[7];
            C[6] = Y[1] * Y[5] - Y[2] * Y[4];
            C[7] = Y[2] * Y[3] - Y[0] * Y[5];
            C[8] = Y[0] * Y[4] - Y[1] * Y[3];
            double det = Y[0] * C[0] + Y[1] * C[1] + Y[2] * C[2];
            double invdet = 1.0 / det;
#pragma unroll
            for (int i = 0; i < 9; ++i)
                Y[i] = 0.5 * (Y[i] + C[i] * invdet);
        }

        for (int i = 0; i < 9; ++i) out[b * 9 + i] = (float)Y[i];
        double t0 = (double)my[0] - (Y[0] * mx[0] + Y[1] * mx[1] + Y[2] * mx[2]);
        double t1 = (double)my[1] - (Y[3] * mx[0] + Y[4] * mx[1] + Y[5] * mx[2]);
        double t2 = (double)my[2] - (Y[6] * mx[0] + Y[7] * mx[1] + Y[8] * mx[2]);
        out[576 + b * 3 + 0] = (float)t0;
        out[576 + b * 3 + 1] = (float)t1;
        out[576 + b * 3 + 2] = (float)t2;
        double xn = sqrt(a[9]), yn = sqrt(a[10]);
        out[768 + b] = (float)(yn / (xn + 1e-6));
    }
}

// ---------------------------------------------------------------------------
extern "C" void kernel_launch(void* const* d_in, const int* in_sizes, int n_in,
                              void* d_out, int out_size) {
    int xi[4], yi[4];
    if (in_sizes[0] == in_sizes[1]) {
        for (int i = 0; i < 4; ++i) { xi[i] = 2 * i; yi[i] = 2 * i + 1; }
    } else {
        for (int i = 0; i < 4; ++i) { xi[i] = i; yi[i] = 4 + i; }
    }
    const float* mu_x = (const float*)d_in[8];
    const float* mu_y = (const float*)d_in[9];
    const float* W    = (const float*)d_in[10];
    const float* Wd   = (const float*)d_in[11];

    static const int chans[4] = {64, 128, 128, 192};
    static const int npts[4]  = {4096, 1024, 256, 64};
    static const int choff[4] = {0, 64, 192, 320};

    MeanArgs A;
    int wb = 0;
    for (int i = 0; i < 4; ++i) {
        for (int side = 0; side < 2; ++side) {
            int t = i * 2 + side;
            A.src[t]      = (const float*)d_in[side == 0 ? xi[i] : yi[i]];
            A.n4[t]       = npts[i] >> 2;
            A.inv_n[t]    = 1.0f / (float)npts[i];
            A.chan[t]     = chans[i];
            A.chan_off[t] = choff[i];
            A.bs_off[t]   = side == 0 ? 0 : 64;
            A.warp_base[t] = wb;
            int rows = 64 * chans[i] * 3;
            wb += (npts[i] == 64) ? rows / 2 : rows;
        }
    }
    A.warp_base[8] = wb;

    mean_fused_kernel<<<(wb + 7) / 8, 256>>>(A);
    vnmlp_kernel<<<dim3(32, 16), 256>>>(W, Wd);
    kabsch_kernel<<<64, 128>>>(mu_x, mu_y, (float*)d_out);
}